// round 4
// baseline (speedup 1.0000x reference)
#include <cuda_runtime.h>

// VectorQuantizer: inputs [131072, 64] f32, embeddings [512, 64] f32
// out (float32 buffer) = codes-as-float [131072]  ++  code_vecs f32 [131072*64]
//
// Two kernels:
//  1) vq_partial: grid = row_tiles x 2 code-halves. Each CTA scans 256 codes
//     for 128 rows, writes packed (dist|idx) per row-half to scratch.
//     2 CTAs/SM (smem ~100KB) -> 4 warps/SMSP to hide LDS latency.
//  2) vq_finalize: combines the 2 halves per row, writes codes (as float)
//     and gathers code vectors.

#define XS_STRIDE 129   // float4 units per dseg row (padded: 128 rows + 1)
// smem: xs 16*129*16 + es 256*16*16 + e2 256*4 + l2r 128*4
#define SMEM1 (16 * XS_STRIDE * 16 + 256 * 16 * 16 + 256 * 4 + 128 * 4)

__device__ unsigned long long vq_scratch[131072 * 2];

__device__ __forceinline__ void fma2(unsigned long long &acc,
                                     unsigned long long a,
                                     unsigned long long b) {
    asm("fma.rn.f32x2 %0, %1, %2, %0;" : "+l"(acc) : "l"(a), "l"(b));
}

__device__ __forceinline__ float2 unpack2(unsigned long long v) {
    float2 r;
    asm("mov.b64 {%0, %1}, %2;" : "=f"(r.x), "=f"(r.y) : "l"(v));
    return r;
}

// order-preserving float -> uint (total order, works for negatives too)
__device__ __forceinline__ unsigned int ford(float f) {
    unsigned int u = __float_as_uint(f);
    return (u & 0x80000000u) ? ~u : (u | 0x80000000u);
}

__global__ __launch_bounds__(256, 2)
void vq_partial(const float4* __restrict__ in4,    // [nrows][16] f4
                const float4* __restrict__ emb4)   // [512][16] f4
{
    extern __shared__ char smem[];
    float4* xs  = (float4*)smem;                 // [16 dseg][XS_STRIDE] f4
    float4* es  = xs + 16 * XS_STRIDE;           // [256 codes][16 dseg] f4
    float*  e2  = (float*)(es + 256 * 16);       // [256] ||e||^2
    float*  l2r = e2 + 256;                      // [128] ||x||^2 per row
    // reused after main loop:
    float* redv = (float*)smem;                  // [8 ct][128 rows]
    int*   redi = (int*)(smem + 4096);           // [8 ct][128 rows]

    const int tid   = threadIdx.x;
    const int tile  = blockIdx.x >> 1;
    const int half  = blockIdx.x & 1;
    const int row0  = tile * 128;
    const int cbase = half * 256;

    // ---- load 128-row input tile, transposed to [dseg][row] ----
    #pragma unroll
    for (int i = 0; i < 8; ++i) {
        int idx  = tid + i * 256;       // 0..2047
        int dseg = idx & 15;
        int r    = idx >> 4;
        xs[dseg * XS_STRIDE + r] = in4[(size_t)(row0 + r) * 16 + dseg];
    }
    // ---- load this half of the embedding table (256 codes) ----
    #pragma unroll
    for (int i = 0; i < 16; ++i) {
        int idx = tid + i * 256;
        es[idx] = emb4[cbase * 16 + idx];
    }
    __syncthreads();

    // ---- e2[c] = ||e_c||^2 ----
    {
        int c = tid;
        if (c < 256) {
            const float4* ep = es + c * 16;
            float s = 0.0f;
            #pragma unroll
            for (int j = 0; j < 16; ++j) {
                float4 v = ep[j];
                s += v.x * v.x + v.y * v.y + v.z * v.z + v.w * v.w;
            }
            e2[c] = s;
        }
    }
    // ---- l2r[r] = ||x_r||^2 ----
    if (tid < 128) {
        float s = 0.0f;
        #pragma unroll
        for (int j = 0; j < 16; ++j) {
            float4 v = xs[j * XS_STRIDE + tid];
            s += v.x * v.x + v.y * v.y + v.z * v.z + v.w * v.w;
        }
        l2r[tid] = s;
    }
    __syncthreads();

    const int rt = tid & 31;   // row thread: rows rt, rt+32, rt+64, rt+96
    const int ct = tid >> 5;   // code thread (warp id): 8 codes per step

    float bestd[4];
    int   besti[4];
    float myl2[4];
    #pragma unroll
    for (int rr = 0; rr < 4; ++rr) {
        bestd[rr] = 3.4e38f; besti[rr] = 0;
        myl2[rr]  = l2r[rt + 32 * rr];
    }

    const ulonglong2* xs2 = (const ulonglong2*)xs;
    const ulonglong2* es2 = (const ulonglong2*)es;

    // ---- main loop: 4 code steps x 64 codes (this half) ----
    for (int cs = 0; cs < 4; ++cs) {
        const int c0 = cs * 64 + ct * 8;   // local code base for this thread

        unsigned long long acc[4][8];
        #pragma unroll
        for (int rr = 0; rr < 4; ++rr)
            #pragma unroll
            for (int cc = 0; cc < 8; ++cc)
                acc[rr][cc] = 0ull;

        #pragma unroll 4
        for (int dseg = 0; dseg < 16; ++dseg) {
            ulonglong2 xv[4];
            #pragma unroll
            for (int rr = 0; rr < 4; ++rr)
                xv[rr] = xs2[dseg * XS_STRIDE + rt + 32 * rr];
            // ev in chunks of 4 to keep live registers <= 128 (2 CTA/SM)
            #pragma unroll
            for (int ch = 0; ch < 2; ++ch) {
                ulonglong2 ev[4];
                #pragma unroll
                for (int cc = 0; cc < 4; ++cc)
                    ev[cc] = es2[(c0 + ch * 4 + cc) * 16 + dseg]; // bcast
                #pragma unroll
                for (int rr = 0; rr < 4; ++rr)
                    #pragma unroll
                    for (int cc = 0; cc < 4; ++cc) {
                        fma2(acc[rr][ch * 4 + cc], xv[rr].x, ev[cc].x);
                        fma2(acc[rr][ch * 4 + cc], xv[rr].y, ev[cc].y);
                    }
            }
        }

        // reference-matching rounding: t = fp32(l2x + e2); dist = fp32(t - 2s)
        #pragma unroll
        for (int cc = 0; cc < 8; ++cc) {
            const int   c  = c0 + cc;
            const float eh = e2[c];
            #pragma unroll
            for (int rr = 0; rr < 4; ++rr) {
                float2 p = unpack2(acc[rr][cc]);
                float  s = p.x + p.y;
                float  t = myl2[rr] + eh;
                float dist = t - 2.0f * s;
                if (dist < bestd[rr]) { bestd[rr] = dist; besti[rr] = c; }
            }
        }
    }

    __syncthreads();   // done reading xs; reuse smem for reduction

    #pragma unroll
    for (int rr = 0; rr < 4; ++rr) {
        int r = rt + 32 * rr;
        redv[ct * 128 + r] = bestd[rr];
        redi[ct * 128 + r] = besti[rr];
    }
    __syncthreads();

    if (tid < 128) {
        float bv = redv[tid];
        int   bi = redi[tid];
        #pragma unroll
        for (int j = 1; j < 8; ++j) {
            float v  = redv[j * 128 + tid];
            int   ii = redi[j * 128 + tid];
            if (v < bv || (v == bv && ii < bi)) { bv = v; bi = ii; }
        }
        // pack: order-preserving dist bits high, global code idx low.
        // equal dist -> lower idx wins; half0 idx < half1 idx always.
        unsigned long long packed =
            ((unsigned long long)ford(bv) << 32) |
            (unsigned int)(cbase + bi);
        vq_scratch[(size_t)(row0 + tid) * 2 + half] = packed;
    }
}

__global__ __launch_bounds__(256)
void vq_finalize(const float4* __restrict__ emb4,   // [512][16] f4
                 float* __restrict__ codes_out,     // [nrows] (as float)
                 float4* __restrict__ vecs_out)     // [nrows][16] f4
{
    int gid  = blockIdx.x * 256 + threadIdx.x;      // over nrows*16
    int row  = gid >> 4;
    int dseg = gid & 15;

    unsigned long long s0 = vq_scratch[(size_t)row * 2 + 0];
    unsigned long long s1 = vq_scratch[(size_t)row * 2 + 1];
    unsigned long long w  = (s1 < s0) ? s1 : s0;
    int idx = (int)(w & 0xFFFFFFFFull);

    if (dseg == 0)
        codes_out[row] = (float)idx;
    vecs_out[(size_t)row * 16 + dseg] = __ldg(emb4 + idx * 16 + dseg);
}

extern "C" void kernel_launch(void* const* d_in, const int* in_sizes, int n_in,
                              void* d_out, int out_size)
{
    const int nrows  = in_sizes[0] / 64;           // 131072
    const int ntiles = nrows / 128;                // 1024

    cudaFuncSetAttribute(vq_partial,
                         cudaFuncAttributeMaxDynamicSharedMemorySize,
                         SMEM1);

    float*  codes = (float*)d_out;
    float4* vecs  = (float4*)((float*)d_out + nrows);

    vq_partial<<<ntiles * 2, 256, SMEM1>>>(
        (const float4*)d_in[0],
        (const float4*)d_in[1]);

    vq_finalize<<<(nrows * 16) / 256, 256>>>(
        (const float4*)d_in[1], codes, vecs);
}